// round 1
// baseline (speedup 1.0000x reference)
#include <cuda_runtime.h>
#include <cuda_bf16.h>
#include <math.h>

// Problem dims
#define BSZ  128     // batch
#define SSZ  256     // sequence
#define ISZ  1024    // input
#define HSZ  1024    // hidden
#define G4   4096    // 4*H
#define CSZ  1000    // classes

// ---------------------------------------------------------------------------
// Scratch (device globals: allocation-free per harness rules)
// ---------------------------------------------------------------------------
__device__ float g_xw[(size_t)SSZ * BSZ * G4];   // [s][b][4H], 512 MB
__device__ float g_h[2][BSZ * HSZ];              // ping-pong hidden state
__device__ float g_c[BSZ * HSZ];                 // cell state (block-private cols)

// ---------------------------------------------------------------------------
// init: zero h0, c0
// ---------------------------------------------------------------------------
__global__ void init_state() {
    int i = blockIdx.x * blockDim.x + threadIdx.x;
    if (i < BSZ * HSZ) {
        g_h[0][i] = 0.0f;
        g_c[i]    = 0.0f;
    }
}

// ---------------------------------------------------------------------------
// Phase 1: xW[s][b][g] = sum_i x[b][s][i] * Wxh[g][i] + bxh[g] + bhh[g]
// Treated as GEMM: A = x viewed [32768, 1024] (row m = b*S+s), B = Wxh [4096,1024]
// Tile 128x128x8, 256 threads, 8x8 per-thread microtile.
// ---------------------------------------------------------------------------
__global__ __launch_bounds__(256, 2) void gemm_xw(
    const float* __restrict__ x, const float* __restrict__ Wxh,
    const float* __restrict__ bxh, const float* __restrict__ bhh)
{
    __shared__ float As[8][128];
    __shared__ float Bs[8][128];

    const int tid = threadIdx.x;
    const int bm = blockIdx.y;          // 0..255  (M tiles)
    const int bn = blockIdx.x;          // 0..31   (N tiles)

    const int lrow = tid >> 1;          // 0..127
    const int lk   = (tid & 1) << 2;    // 0 or 4
    const float* Ap = x   + (size_t)(bm * 128 + lrow) * ISZ + lk;
    const float* Bp = Wxh + (size_t)(bn * 128 + lrow) * ISZ + lk;

    const int tx = tid & 15;            // N direction, 16 threads
    const int ty = tid >> 4;            // M direction, 16 threads

    float acc[8][8];
#pragma unroll
    for (int i = 0; i < 8; i++)
#pragma unroll
        for (int j = 0; j < 8; j++) acc[i][j] = 0.0f;

    for (int k0 = 0; k0 < ISZ; k0 += 8) {
        float4 av = *reinterpret_cast<const float4*>(Ap + k0);
        float4 bv = *reinterpret_cast<const float4*>(Bp + k0);
        __syncthreads();
        As[lk + 0][lrow] = av.x; As[lk + 1][lrow] = av.y;
        As[lk + 2][lrow] = av.z; As[lk + 3][lrow] = av.w;
        Bs[lk + 0][lrow] = bv.x; Bs[lk + 1][lrow] = bv.y;
        Bs[lk + 2][lrow] = bv.z; Bs[lk + 3][lrow] = bv.w;
        __syncthreads();
#pragma unroll
        for (int kk = 0; kk < 8; kk++) {
            float a[8], b[8];
            *reinterpret_cast<float4*>(a)     = *reinterpret_cast<const float4*>(&As[kk][ty * 8]);
            *reinterpret_cast<float4*>(a + 4) = *reinterpret_cast<const float4*>(&As[kk][ty * 8 + 4]);
            *reinterpret_cast<float4*>(b)     = *reinterpret_cast<const float4*>(&Bs[kk][tx * 8]);
            *reinterpret_cast<float4*>(b + 4) = *reinterpret_cast<const float4*>(&Bs[kk][tx * 8 + 4]);
#pragma unroll
            for (int i = 0; i < 8; i++)
#pragma unroll
                for (int j = 0; j < 8; j++)
                    acc[i][j] = fmaf(a[i], b[j], acc[i][j]);
        }
    }

    // epilogue: bias + scatter rows to [s][b][g]
    const int gbase = bn * 128 + tx * 8;
    float bias[8];
#pragma unroll
    for (int j = 0; j < 8; j++) bias[j] = bxh[gbase + j] + bhh[gbase + j];

#pragma unroll
    for (int i = 0; i < 8; i++) {
        const int m = bm * 128 + ty * 8 + i;
        const int s = m & (SSZ - 1);
        const int b = m >> 8;            // m / 256
        float* orow = g_xw + ((size_t)s * BSZ + b) * G4 + gbase;
        float4 o0, o1;
        o0.x = acc[i][0] + bias[0]; o0.y = acc[i][1] + bias[1];
        o0.z = acc[i][2] + bias[2]; o0.w = acc[i][3] + bias[3];
        o1.x = acc[i][4] + bias[4]; o1.y = acc[i][5] + bias[5];
        o1.z = acc[i][6] + bias[6]; o1.w = acc[i][7] + bias[7];
        *reinterpret_cast<float4*>(orow)     = o0;
        *reinterpret_cast<float4*>(orow + 4) = o1;
    }
}

// ---------------------------------------------------------------------------
// Phase 2: one LSTM step. 128 blocks, block owns 8 hidden cols (=32 gate cols).
// gates[b][g] = g_xw[t][b][g] + sum_k h_in[b][k] * Whh[g][k], then gate math.
// h double-buffered (cross-block hazard), c in place (block-private columns).
// ---------------------------------------------------------------------------
__global__ __launch_bounds__(256) void lstm_step(
    const float* __restrict__ Whh, int t)
{
    __shared__ float Hs[16][128];
    __shared__ float Ws[16][32];

    const float* __restrict__ h_in  = g_h[t & 1];
    float* __restrict__       h_out = g_h[(t + 1) & 1];

    const int tid = threadIdx.x;
    const int tx = tid & 7;     // hidden col within block
    const int ty = tid >> 3;    // 0..31 batch group (4 rows each)
    const int hbase = blockIdx.x * 8;

    // Hs load mapping: 2048 floats = 512 float4, 2 per thread, same row
    const int hidx = tid * 2;           // even
    const int hrow = hidx >> 2;         // 0..127
    const int hkq  = hidx & 3;          // 0 or 2
    const float* hp_base = h_in + (size_t)hrow * HSZ + hkq * 4;

    // Ws load mapping: tid < 128 loads one float4
    const int wcol = tid >> 2;                               // 0..31
    const int wkq  = tid & 3;                                // 0..3
    const int wg   = (wcol >> 3) * HSZ + hbase + (wcol & 7); // gate*1024 + hidden col
    const float* wp_base = Whh + (size_t)wg * HSZ + wkq * 4;

    float acc[4][4];  // [gate][row]
#pragma unroll
    for (int q = 0; q < 4; q++)
#pragma unroll
        for (int r = 0; r < 4; r++) acc[q][r] = 0.0f;

    for (int k0 = 0; k0 < HSZ; k0 += 16) {
        float4 v0 = *reinterpret_cast<const float4*>(hp_base + k0);
        float4 v1 = *reinterpret_cast<const float4*>(hp_base + k0 + 4);
        float4 wv;
        if (tid < 128) wv = *reinterpret_cast<const float4*>(wp_base + k0);
        __syncthreads();
        Hs[hkq * 4 + 0][hrow] = v0.x; Hs[hkq * 4 + 1][hrow] = v0.y;
        Hs[hkq * 4 + 2][hrow] = v0.z; Hs[hkq * 4 + 3][hrow] = v0.w;
        Hs[hkq * 4 + 4][hrow] = v1.x; Hs[hkq * 4 + 5][hrow] = v1.y;
        Hs[hkq * 4 + 6][hrow] = v1.z; Hs[hkq * 4 + 7][hrow] = v1.w;
        if (tid < 128) {
            Ws[wkq * 4 + 0][wcol] = wv.x; Ws[wkq * 4 + 1][wcol] = wv.y;
            Ws[wkq * 4 + 2][wcol] = wv.z; Ws[wkq * 4 + 3][wcol] = wv.w;
        }
        __syncthreads();
#pragma unroll
        for (int kk = 0; kk < 16; kk++) {
            float a[4];
            *reinterpret_cast<float4*>(a) = *reinterpret_cast<const float4*>(&Hs[kk][ty * 4]);
            const float w0 = Ws[kk][tx];
            const float w1 = Ws[kk][8 + tx];
            const float w2 = Ws[kk][16 + tx];
            const float w3 = Ws[kk][24 + tx];
#pragma unroll
            for (int r = 0; r < 4; r++) {
                acc[0][r] = fmaf(w0, a[r], acc[0][r]);
                acc[1][r] = fmaf(w1, a[r], acc[1][r]);
                acc[2][r] = fmaf(w2, a[r], acc[2][r]);
                acc[3][r] = fmaf(w3, a[r], acc[3][r]);
            }
        }
    }

    // gate epilogue
    const float* xwt = g_xw + (size_t)t * BSZ * G4;
    const int hcol = hbase + tx;
#pragma unroll
    for (int r = 0; r < 4; r++) {
        const int row = ty * 4 + r;
        const float* xb = xwt + (size_t)row * G4;
        const float gi = acc[0][r] + xb[hcol];
        const float gf = acc[1][r] + xb[HSZ + hcol];
        const float gg = acc[2][r] + xb[2 * HSZ + hcol];
        const float go = acc[3][r] + xb[3 * HSZ + hcol];
        const float it = 1.0f / (1.0f + expf(-gi));
        const float ft = 1.0f / (1.0f + expf(-gf));
        const float ot = 1.0f / (1.0f + expf(-go));
        const float ch = tanhf(gg);
        const int ci = row * HSZ + hcol;
        const float cn = g_c[ci] * ft + it * ch;
        g_c[ci] = cn;
        h_out[ci] = ot * tanhf(cn);
    }
}

// ---------------------------------------------------------------------------
// Phase 3: out[b][c] = sum_k h_last[b][k] * Wfc[c][k] + bfc[c]
// After 256 steps h_last lives in g_h[0].
// ---------------------------------------------------------------------------
__global__ __launch_bounds__(256) void fc_out(
    const float* __restrict__ Wfc, const float* __restrict__ bfc,
    float* __restrict__ out)
{
    __shared__ float hs[HSZ];
    const int b = blockIdx.x;
    const float* hrow = g_h[0] + (size_t)b * HSZ;
    for (int i = threadIdx.x; i < HSZ; i += 256) hs[i] = hrow[i];
    __syncthreads();

    for (int cc = threadIdx.x; cc < CSZ; cc += 256) {
        const float* wr = Wfc + (size_t)cc * HSZ;
        float acc = 0.0f;
#pragma unroll 4
        for (int k = 0; k < HSZ; k += 4) {
            float4 w = *reinterpret_cast<const float4*>(wr + k);
            acc = fmaf(hs[k + 0], w.x, acc);
            acc = fmaf(hs[k + 1], w.y, acc);
            acc = fmaf(hs[k + 2], w.z, acc);
            acc = fmaf(hs[k + 3], w.w, acc);
        }
        out[b * CSZ + cc] = acc + bfc[cc];
    }
}

// ---------------------------------------------------------------------------
// launch
// ---------------------------------------------------------------------------
extern "C" void kernel_launch(void* const* d_in, const int* in_sizes, int n_in,
                              void* d_out, int out_size) {
    const float* x   = (const float*)d_in[0];
    const float* Wxh = (const float*)d_in[1];
    const float* bxh = (const float*)d_in[2];
    const float* Whh = (const float*)d_in[3];
    const float* bhh = (const float*)d_in[4];
    const float* Wfc = (const float*)d_in[5];
    const float* bfc = (const float*)d_in[6];
    float* out = (float*)d_out;

    init_state<<<(BSZ * HSZ + 255) / 256, 256>>>();

    dim3 g1(G4 / 128, (BSZ * SSZ) / 128);   // (32, 256)
    gemm_xw<<<g1, 256>>>(x, Wxh, bxh, bhh);

    for (int t = 0; t < SSZ; t++)
        lstm_step<<<HSZ / 8, 256>>>(Whh, t);

    fc_out<<<BSZ, 256>>>(Wfc, bfc, out);
}

// round 3
// speedup vs baseline: 2.3118x; 2.3118x over previous
#include <cuda_runtime.h>
#include <cuda_bf16.h>
#include <cstdint>
#include <math.h>

#define BSZ 128
#define SSZ 256
#define ISZ 1024
#define HSZ 1024
#define G4  4096
#define CSZ 1000

// ---------------------------------------------------------------------------
// Device-global scratch
// ---------------------------------------------------------------------------
__device__ float g_xw[(size_t)SSZ * G4 * BSZ];              // [s][g][b] fp32
__device__ __nv_bfloat16 g_xhi[(size_t)BSZ * SSZ * ISZ];    // x split hi  [b][s][k]
__device__ __nv_bfloat16 g_xlo[(size_t)BSZ * SSZ * ISZ];
__device__ __nv_bfloat16 g_wxhi[(size_t)G4 * ISZ];
__device__ __nv_bfloat16 g_wxlo[(size_t)G4 * ISZ];
__device__ __nv_bfloat16 g_whhi[(size_t)G4 * HSZ];
__device__ __nv_bfloat16 g_whlo[(size_t)G4 * HSZ];
__device__ __nv_bfloat16 g_hhi[2][BSZ * HSZ];               // h ping-pong hi [b][k]
__device__ __nv_bfloat16 g_hlo[2][BSZ * HSZ];
__device__ float g_c[HSZ * BSZ];                            // c, [hc][b]

// ---------------------------------------------------------------------------
// PTX helpers (sm_103 baseline features only: ldmatrix / mma.sync / cp.async)
// ---------------------------------------------------------------------------
__device__ __forceinline__ uint32_t smem_u32(const void* p) {
    uint32_t a;
    asm("{ .reg .u64 t; cvta.to.shared.u64 t, %1; cvt.u32.u64 %0, t; }"
        : "=r"(a) : "l"(p));
    return a;
}

#define CP16(s, g) \
    asm volatile("cp.async.cg.shared.global [%0], [%1], 16;" :: "r"(s), "l"(g))
#define CP_COMMIT() asm volatile("cp.async.commit_group;" ::: "memory")
#define CP_WAIT1()  asm volatile("cp.async.wait_group 1;" ::: "memory")

__device__ __forceinline__ void ldmx4(uint32_t* r, uint32_t addr) {
    asm volatile("ldmatrix.sync.aligned.m8n8.x4.shared.b16 {%0,%1,%2,%3}, [%4];"
        : "=r"(r[0]), "=r"(r[1]), "=r"(r[2]), "=r"(r[3]) : "r"(addr));
}

__device__ __forceinline__ void mma16816(float* d, const uint32_t* a, const uint32_t* b) {
    asm volatile(
        "mma.sync.aligned.m16n8k16.row.col.f32.bf16.bf16.f32 "
        "{%0,%1,%2,%3}, {%4,%5,%6,%7}, {%8,%9}, {%0,%1,%2,%3};"
        : "+f"(d[0]), "+f"(d[1]), "+f"(d[2]), "+f"(d[3])
        : "r"(a[0]), "r"(a[1]), "r"(a[2]), "r"(a[3]), "r"(b[0]), "r"(b[1]));
}

__device__ __forceinline__ float sigf(float x) { return 1.0f / (1.0f + __expf(-x)); }
__device__ __forceinline__ float tanh_fast(float x) {
    float e = __expf(fminf(fmaxf(2.0f * x, -30.0f), 30.0f));
    return __fdividef(e - 1.0f, e + 1.0f);
}

// ---------------------------------------------------------------------------
// split fp32 -> (hi, lo) bf16
// ---------------------------------------------------------------------------
__global__ void split_k(const float* __restrict__ src, int sel, int n4) {
    __nv_bfloat16 *hi, *lo;
    if (sel == 0)      { hi = g_xhi;  lo = g_xlo;  }
    else if (sel == 1) { hi = g_wxhi; lo = g_wxlo; }
    else               { hi = g_whhi; lo = g_whlo; }
    int i = blockIdx.x * blockDim.x + threadIdx.x;
    if (i >= n4) return;
    float4 v = reinterpret_cast<const float4*>(src)[i];
    __nv_bfloat16 h0 = __float2bfloat16(v.x), h1 = __float2bfloat16(v.y);
    __nv_bfloat16 h2 = __float2bfloat16(v.z), h3 = __float2bfloat16(v.w);
    __nv_bfloat162 a, b;
    a.x = h0; a.y = h1; b.x = h2; b.y = h3;
    reinterpret_cast<__nv_bfloat162*>(hi)[2 * i]     = a;
    reinterpret_cast<__nv_bfloat162*>(hi)[2 * i + 1] = b;
    a.x = __float2bfloat16(v.x - __bfloat162float(h0));
    a.y = __float2bfloat16(v.y - __bfloat162float(h1));
    b.x = __float2bfloat16(v.z - __bfloat162float(h2));
    b.y = __float2bfloat16(v.w - __bfloat162float(h3));
    reinterpret_cast<__nv_bfloat162*>(lo)[2 * i]     = a;
    reinterpret_cast<__nv_bfloat162*>(lo)[2 * i + 1] = b;
}

__global__ void init_state() {
    int i = blockIdx.x * blockDim.x + threadIdx.x;
    if (i < BSZ * HSZ) {
        g_hhi[0][i] = __float2bfloat16(0.0f);
        g_hlo[0][i] = __float2bfloat16(0.0f);
        g_c[i] = 0.0f;
    }
}

// ---------------------------------------------------------------------------
// Phase 1: xw[s][g][b], M=128 (batch, one s per M-tile), N=128 gates/CTA.
// Virtual K = 3072: seg0 Ah*Bh, seg1 Al*Bh, seg2 Ah*Bl. K-chunk 64 elems.
// smem: 2 stages of (A 128x144B + B 128x144B) = 73728; epilogue f32 tile
// [128g][132 pitch] overlaps stages; bias at 73728.
// ---------------------------------------------------------------------------
#define PITCH     144
#define P1_STAGE  36864
#define P1_BOFF   18432
#define P1_BIAS   73728
#define P1_SMEM   74240
#define NCHUNK    48

__global__ __launch_bounds__(256, 2) void gemm_xw_tc(const float* __restrict__ bxh,
                                                     const float* __restrict__ bhh) {
    extern __shared__ char sm[];
    const uint32_t sb = smem_u32(sm);
    const int tid = threadIdx.x;
    const int wid = tid >> 5, lane = tid & 31;
    const int s  = blockIdx.y;
    const int n0 = blockIdx.x * 128;

    float* sbias = reinterpret_cast<float*>(sm + P1_BIAS);
    if (tid < 128) sbias[tid] = bxh[n0 + tid] + bhh[n0 + tid];

    const int wm = wid >> 2, wn = wid & 3;

    // loader: 128 rows x 8 quads per matrix, 4 iters/thread each
    const int lrow = tid >> 3, lq = tid & 7;   // +32 rows per iter

    auto load_stage = [&](int c, int buf) {
        const int seg  = c >> 4;
        const int koff = (c & 15) * 64 + lq * 8;
        const __nv_bfloat16* Asrc = (seg == 1) ? g_xlo  : g_xhi;
        const __nv_bfloat16* Bsrc = (seg == 2) ? g_wxlo : g_wxhi;
        uint32_t Ab = sb + buf * P1_STAGE + lrow * PITCH + lq * 16;
        uint32_t Bb = Ab + P1_BOFF;
#pragma unroll
        for (int i = 0; i < 4; i++) {
            int row = lrow + i * 32;
            CP16(Ab + i * 32 * PITCH, Asrc + (((size_t)((row << 8) + s)) << 10) + koff);
            CP16(Bb + i * 32 * PITCH, Bsrc + (((size_t)(n0 + row)) << 10) + koff);
        }
        CP_COMMIT();
    };

    load_stage(0, 0);
    load_stage(1, 1);

    float d[4][4][4];
#pragma unroll
    for (int i = 0; i < 4; i++)
#pragma unroll
        for (int j = 0; j < 4; j++)
#pragma unroll
            for (int k = 0; k < 4; k++) d[i][j][k] = 0.0f;

    // ldmatrix per-thread row offsets
    const uint32_t a_r  = (uint32_t)(lane & 15) * PITCH + ((lane >> 4) << 4);
    const uint32_t b_r  = (uint32_t)((lane & 7) + ((lane & 16) >> 1)) * PITCH
                        + (((lane >> 3) & 1) << 4);

    for (int c = 0; c < NCHUNK; c++) {
        CP_WAIT1();
        __syncthreads();
        const uint32_t Ab = sb + (c & 1) * P1_STAGE;
        const uint32_t Bb = Ab + P1_BOFF;
#pragma unroll
        for (int s2 = 0; s2 < 4; s2++) {
            uint32_t a[4][4], b[2][4];
#pragma unroll
            for (int mt = 0; mt < 4; mt++)
                ldmx4(a[mt], Ab + (uint32_t)(wm * 64 + mt * 16) * PITCH + s2 * 32 + a_r);
#pragma unroll
            for (int nt = 0; nt < 2; nt++)
                ldmx4(b[nt], Bb + (uint32_t)(wn * 32 + nt * 16) * PITCH + s2 * 32 + b_r);
#pragma unroll
            for (int mt = 0; mt < 4; mt++)
#pragma unroll
                for (int n8 = 0; n8 < 4; n8++)
                    mma16816(d[mt][n8], a[mt], &b[n8 >> 1][(n8 & 1) * 2]);
        }
        __syncthreads();
        if (c + 2 < NCHUNK) load_stage(c + 2, c & 1);
    }

    // epilogue: transpose through smem, coalesced writeout with bias
    __syncthreads();
    float* tile = reinterpret_cast<float*>(sm);  // [g:128][pitch 132] -> value at col b
    const int fr = lane >> 2, fc = (lane & 3) * 2;
#pragma unroll
    for (int mt = 0; mt < 4; mt++)
#pragma unroll
        for (int n8 = 0; n8 < 4; n8++) {
            int r0 = wm * 64 + mt * 16 + fr;
            int cc = wn * 32 + n8 * 8 + fc;
            tile[(size_t)cc * 132 + r0]           = d[mt][n8][0];
            tile[(size_t)(cc + 1) * 132 + r0]     = d[mt][n8][1];
            tile[(size_t)cc * 132 + r0 + 8]       = d[mt][n8][2];
            tile[(size_t)(cc + 1) * 132 + r0 + 8] = d[mt][n8][3];
        }
    __syncthreads();
#pragma unroll
    for (int it = 0; it < 16; it++) {
        int u = tid + it * 256;          // 4096 float4s
        int g = u >> 5, q = u & 31;
        float4 v = *reinterpret_cast<const float4*>(tile + (size_t)g * 132 + q * 4);
        float bi = sbias[g];
        v.x += bi; v.y += bi; v.z += bi; v.w += bi;
        *reinterpret_cast<float4*>(g_xw + ((size_t)s * G4 + n0 + g) * BSZ + q * 4) = v;
    }
}

// ---------------------------------------------------------------------------
// Phase 2: one LSTM step. Grid (64, 2): j = 16-hidden-col group, mh = batch half.
// CTA: M=64 (batch) x N=64 (4 gates x 16 hidden), K=3072 virtual.
// Warps: 2 (M) x 4 (gate). Fused gate epilogue.
// smem: 2 stages of (A 64x144 + B 64x144) = 36864; sg f32 [64][65] overlaps;
// sh f32 [64][16] at 36864.
// ---------------------------------------------------------------------------
#define P2_STAGE 18432
#define P2_BOFF  9216
#define P2_SH    36864
#define P2_SMEM  40960

__global__ __launch_bounds__(256, 2) void lstm_tc(int t) {
    extern __shared__ char sm[];
    const uint32_t sb = smem_u32(sm);
    const int tid = threadIdx.x;
    const int wid = tid >> 5, lane = tid & 31;
    const int j = blockIdx.x;      // hidden col group (16)
    const int mh = blockIdx.y;     // batch half

    const __nv_bfloat16* __restrict__ hin_hi = g_hhi[t & 1];
    const __nv_bfloat16* __restrict__ hin_lo = g_hlo[t & 1];
    __nv_bfloat16* __restrict__ hout_hi = g_hhi[(t + 1) & 1];
    __nv_bfloat16* __restrict__ hout_lo = g_hlo[(t + 1) & 1];

    const int wm = wid >> 2, gi = wid & 3;

    // loader: 64 rows x 8 quads per matrix -> 512 ops per matrix, 2/thread
    const int lrow = tid >> 3, lq = tid & 7;  // rows 0..31, +32 second iter

    auto load_stage = [&](int c, int buf) {
        const int seg  = c >> 4;
        const int koff = (c & 15) * 64 + lq * 8;
        const __nv_bfloat16* Asrc = (seg == 1) ? hin_lo : hin_hi;
        const __nv_bfloat16* Bsrc = (seg == 2) ? g_whlo : g_whhi;
        uint32_t Ab = sb + buf * P2_STAGE + lrow * PITCH + lq * 16;
        uint32_t Bb = Ab + P2_BOFF;
#pragma unroll
        for (int i = 0; i < 2; i++) {
            int row = lrow + i * 32;
            CP16(Ab + i * 32 * PITCH,
                 Asrc + ((size_t)(mh * 64 + row) << 10) + koff);
            int grow = (row >> 4) * HSZ + j * 16 + (row & 15);
            CP16(Bb + i * 32 * PITCH,
                 Bsrc + ((size_t)grow << 10) + koff);
        }
        CP_COMMIT();
    };

    load_stage(0, 0);
    load_stage(1, 1);

    float d[2][2][4];
#pragma unroll
    for (int i = 0; i < 2; i++)
#pragma unroll
        for (int jj = 0; jj < 2; jj++)
#pragma unroll
            for (int k = 0; k < 4; k++) d[i][jj][k] = 0.0f;

    const uint32_t a_r = (uint32_t)(lane & 15) * PITCH + ((lane >> 4) << 4);
    const uint32_t b_r = (uint32_t)((lane & 7) + ((lane & 16) >> 1)) * PITCH
                       + (((lane >> 3) & 1) << 4);

    for (int c = 0; c < NCHUNK; c++) {
        CP_WAIT1();
        __syncthreads();
        const uint32_t Ab = sb + (c & 1) * P2_STAGE;
        const uint32_t Bb = Ab + P2_BOFF;
#pragma unroll
        for (int s2 = 0; s2 < 4; s2++) {
            uint32_t a[2][4], b[4];
#pragma unroll
            for (int mt = 0; mt < 2; mt++)
                ldmx4(a[mt], Ab + (uint32_t)(wm * 32 + mt * 16) * PITCH + s2 * 32 + a_r);
            ldmx4(b, Bb + (uint32_t)(gi * 16) * PITCH + s2 * 32 + b_r);
#pragma unroll
            for (int mt = 0; mt < 2; mt++)
#pragma unroll
                for (int n8 = 0; n8 < 2; n8++)
                    mma16816(d[mt][n8], a[mt], &b[n8 * 2]);
        }
        __syncthreads();
        if (c + 2 < NCHUNK) load_stage(c + 2, c & 1);
    }

    // gates to smem: sg[b_local][gate*16 + hc], pitch 65
    __syncthreads();
    float* sg = reinterpret_cast<float*>(sm);
    const int fr = lane >> 2, fc = (lane & 3) * 2;
#pragma unroll
    for (int mt = 0; mt < 2; mt++)
#pragma unroll
        for (int n8 = 0; n8 < 2; n8++) {
            int r0 = wm * 32 + mt * 16 + fr;
            int cc = gi * 16 + n8 * 8 + fc;
            sg[(size_t)r0 * 65 + cc]           = d[mt][n8][0];
            sg[(size_t)r0 * 65 + cc + 1]       = d[mt][n8][1];
            sg[(size_t)(r0 + 8) * 65 + cc]     = d[mt][n8][2];
            sg[(size_t)(r0 + 8) * 65 + cc + 1] = d[mt][n8][3];
        }
    __syncthreads();

    // fused gate math: thread -> (b_local = tid&63, 4 hc values)
    float* sh = reinterpret_cast<float*>(sm + P2_SH);   // [64][16]
    {
        const int bl = tid & 63, hq = tid >> 6;
        const float* xwb = g_xw + (size_t)t * G4 * BSZ;
        const int bg = mh * 64 + bl;
#pragma unroll
        for (int ii = 0; ii < 4; ii++) {
            const int hc = hq * 4 + ii;
            const int gcol = j * 16 + hc;
            float vi = sg[(size_t)bl * 65 + hc]      + xwb[(size_t)gcol * BSZ + bg];
            float vf = sg[(size_t)bl * 65 + 16 + hc] + xwb[(size_t)(HSZ + gcol) * BSZ + bg];
            float vg = sg[(size_t)bl * 65 + 32 + hc] + xwb[(size_t)(2 * HSZ + gcol) * BSZ + bg];
            float vo = sg[(size_t)bl * 65 + 48 + hc] + xwb[(size_t)(3 * HSZ + gcol) * BSZ + bg];
            float ig = sigf(vi), fg = sigf(vf), og = sigf(vo);
            float ch = tanh_fast(vg);
            const int ci = gcol * BSZ + bg;
            float cn = g_c[ci] * fg + ig * ch;
            g_c[ci] = cn;
            sh[bl * 16 + hc] = og * tanh_fast(cn);
        }
    }
    __syncthreads();

    // h writeout: split to bf16 hi/lo, 16B stores
    if (tid < 128) {
        const int b = tid >> 1, half = tid & 1;
        const float* src = sh + b * 16 + half * 8;
        __align__(16) __nv_bfloat16 hi8[8], lo8[8];
#pragma unroll
        for (int i = 0; i < 8; i++) {
            float v = src[i];
            __nv_bfloat16 h = __float2bfloat16(v);
            hi8[i] = h;
            lo8[i] = __float2bfloat16(v - __bfloat162float(h));
        }
        size_t dst = ((size_t)(mh * 64 + b) << 10) + j * 16 + half * 8;
        *reinterpret_cast<uint4*>(hout_hi + dst) = *reinterpret_cast<const uint4*>(hi8);
        *reinterpret_cast<uint4*>(hout_lo + dst) = *reinterpret_cast<const uint4*>(lo8);
    }
}

// ---------------------------------------------------------------------------
// Phase 3: out[b][c] = h_last . Wfc[c] + bfc[c]
// ---------------------------------------------------------------------------
__global__ __launch_bounds__(256) void fc_out(const float* __restrict__ Wfc,
                                              const float* __restrict__ bfc,
                                              float* __restrict__ out) {
    __shared__ float hs[HSZ];
    const int b = blockIdx.x;
    for (int i = threadIdx.x; i < HSZ; i += 256)
        hs[i] = __bfloat162float(g_hhi[0][b * HSZ + i]) + __bfloat162float(g_hlo[0][b * HSZ + i]);
    __syncthreads();

    for (int cc = threadIdx.x; cc < CSZ; cc += 256) {
        const float* wr = Wfc + (size_t)cc * HSZ;
        float acc = 0.0f;
#pragma unroll 4
        for (int k = 0; k < HSZ; k += 4) {
            float4 w = *reinterpret_cast<const float4*>(wr + k);
            acc = fmaf(hs[k + 0], w.x, acc);
            acc = fmaf(hs[k + 1], w.y, acc);
            acc = fmaf(hs[k + 2], w.z, acc);
            acc = fmaf(hs[k + 3], w.w, acc);
        }
        out[b * CSZ + cc] = acc + bfc[cc];
    }
}

// ---------------------------------------------------------------------------
// launch
// ---------------------------------------------------------------------------
extern "C" void kernel_launch(void* const* d_in, const int* in_sizes, int n_in,
                              void* d_out, int out_size) {
    const float* x   = (const float*)d_in[0];
    const float* Wxh = (const float*)d_in[1];
    const float* bxh = (const float*)d_in[2];
    const float* Whh = (const float*)d_in[3];
    const float* bhh = (const float*)d_in[4];
    const float* Wfc = (const float*)d_in[5];
    const float* bfc = (const float*)d_in[6];
    float* out = (float*)d_out;

    cudaFuncSetAttribute(gemm_xw_tc, cudaFuncAttributeMaxDynamicSharedMemorySize, P1_SMEM);
    cudaFuncSetAttribute(lstm_tc,    cudaFuncAttributeMaxDynamicSharedMemorySize, P2_SMEM);

    {
        int n4 = (BSZ * SSZ * ISZ) / 4;
        split_k<<<(n4 + 255) / 256, 256>>>(x, 0, n4);
        n4 = (G4 * ISZ) / 4;
        split_k<<<(n4 + 255) / 256, 256>>>(Wxh, 1, n4);
        n4 = (G4 * HSZ) / 4;
        split_k<<<(n4 + 255) / 256, 256>>>(Whh, 2, n4);
    }
    init_state<<<(BSZ * HSZ + 255) / 256, 256>>>();

    dim3 g1(G4 / 128, SSZ);   // (32, 256)
    gemm_xw_tc<<<g1, 256, P1_SMEM>>>(bxh, bhh);

    dim3 g2(HSZ / 16, 2);     // (64, 2)
    for (int t = 0; t < SSZ; t++)
        lstm_tc<<<g2, 256, P2_SMEM>>>(t);

    fc_out<<<BSZ, 256>>>(Wfc, bfc, out);
}

// round 4
// speedup vs baseline: 2.5636x; 1.1089x over previous
#include <cuda_runtime.h>
#include <cuda_bf16.h>
#include <cstdint>
#include <math.h>

#define BSZ 128
#define SSZ 256
#define ISZ 1024
#define HSZ 1024
#define G4  4096
#define CSZ 1000

// ---------------------------------------------------------------------------
// Device-global scratch
// ---------------------------------------------------------------------------
__device__ float g_xw[(size_t)SSZ * G4 * BSZ];              // [s][g][b] fp32
__device__ __nv_bfloat16 g_xhi[(size_t)BSZ * SSZ * ISZ];    // x split hi  [b][s][k]
__device__ __nv_bfloat16 g_xlo[(size_t)BSZ * SSZ * ISZ];
__device__ __nv_bfloat16 g_wxhi[(size_t)G4 * ISZ];
__device__ __nv_bfloat16 g_wxlo[(size_t)G4 * ISZ];
__device__ __nv_bfloat16 g_whhi[(size_t)G4 * HSZ];
__device__ __nv_bfloat16 g_whlo[(size_t)G4 * HSZ];
__device__ __nv_bfloat16 g_hhi[2][BSZ * HSZ];               // h ping-pong hi [b][k]
__device__ __nv_bfloat16 g_hlo[2][BSZ * HSZ];
__device__ float g_c[HSZ * BSZ];                            // c, [hc][b]

// ---------------------------------------------------------------------------
// PTX helpers (sm_103 baseline: ldmatrix / mma.sync / cp.async)
// ---------------------------------------------------------------------------
__device__ __forceinline__ uint32_t smem_u32(const void* p) {
    uint32_t a;
    asm("{ .reg .u64 t; cvta.to.shared.u64 t, %1; cvt.u32.u64 %0, t; }"
        : "=r"(a) : "l"(p));
    return a;
}

#define CP16(s, g) \
    asm volatile("cp.async.cg.shared.global [%0], [%1], 16;" :: "r"(s), "l"(g))
#define CP_COMMIT() asm volatile("cp.async.commit_group;" ::: "memory")
#define CP_WAIT1()  asm volatile("cp.async.wait_group 1;" ::: "memory")

__device__ __forceinline__ void ldmx4(uint32_t* r, uint32_t addr) {
    asm volatile("ldmatrix.sync.aligned.m8n8.x4.shared.b16 {%0,%1,%2,%3}, [%4];"
        : "=r"(r[0]), "=r"(r[1]), "=r"(r[2]), "=r"(r[3]) : "r"(addr));
}

__device__ __forceinline__ void mma16816(float* d, const uint32_t* a, const uint32_t* b) {
    asm volatile(
        "mma.sync.aligned.m16n8k16.row.col.f32.bf16.bf16.f32 "
        "{%0,%1,%2,%3}, {%4,%5,%6,%7}, {%8,%9}, {%0,%1,%2,%3};"
        : "+f"(d[0]), "+f"(d[1]), "+f"(d[2]), "+f"(d[3])
        : "r"(a[0]), "r"(a[1]), "r"(a[2]), "r"(a[3]), "r"(b[0]), "r"(b[1]));
}

__device__ __forceinline__ float sigf(float x) { return 1.0f / (1.0f + __expf(-x)); }
__device__ __forceinline__ float tanh_fast(float x) {
    float e = __expf(fminf(fmaxf(2.0f * x, -30.0f), 30.0f));
    return __fdividef(e - 1.0f, e + 1.0f);
}

// ---------------------------------------------------------------------------
// split fp32 -> (hi, lo) bf16
// ---------------------------------------------------------------------------
__global__ void split_k(const float* __restrict__ src, int sel, int n4) {
    __nv_bfloat16 *hi, *lo;
    if (sel == 0)      { hi = g_xhi;  lo = g_xlo;  }
    else if (sel == 1) { hi = g_wxhi; lo = g_wxlo; }
    else               { hi = g_whhi; lo = g_whlo; }
    int i = blockIdx.x * blockDim.x + threadIdx.x;
    if (i >= n4) return;
    float4 v = reinterpret_cast<const float4*>(src)[i];
    __nv_bfloat16 h0 = __float2bfloat16(v.x), h1 = __float2bfloat16(v.y);
    __nv_bfloat16 h2 = __float2bfloat16(v.z), h3 = __float2bfloat16(v.w);
    __nv_bfloat162 a, b;
    a.x = h0; a.y = h1; b.x = h2; b.y = h3;
    reinterpret_cast<__nv_bfloat162*>(hi)[2 * i]     = a;
    reinterpret_cast<__nv_bfloat162*>(hi)[2 * i + 1] = b;
    a.x = __float2bfloat16(v.x - __bfloat162float(h0));
    a.y = __float2bfloat16(v.y - __bfloat162float(h1));
    b.x = __float2bfloat16(v.z - __bfloat162float(h2));
    b.y = __float2bfloat16(v.w - __bfloat162float(h3));
    reinterpret_cast<__nv_bfloat162*>(lo)[2 * i]     = a;
    reinterpret_cast<__nv_bfloat162*>(lo)[2 * i + 1] = b;
}

__global__ void init_state() {
    int i = blockIdx.x * blockDim.x + threadIdx.x;
    if (i < BSZ * HSZ) {
        g_hhi[0][i] = __float2bfloat16(0.0f);
        g_hlo[0][i] = __float2bfloat16(0.0f);
        g_c[i] = 0.0f;
    }
}

// ---------------------------------------------------------------------------
// Phase 1: xw[s][g][b], M=128 (batch), N=128 gates/CTA, virtual K=3072.
// 3 smem buffers, 2 outstanding cp.async groups, 1 sync per chunk.
// ---------------------------------------------------------------------------
#define PITCH     144
#define P1_STG    36864
#define P1_BOFF   18432
#define P1_BIAS   110592
#define P1_SMEM   111104
#define NCHUNK    48

__global__ __launch_bounds__(256, 2) void gemm_xw_tc(const float* __restrict__ bxh,
                                                     const float* __restrict__ bhh) {
    extern __shared__ char sm[];
    const uint32_t sb = smem_u32(sm);
    const int tid = threadIdx.x;
    const int wid = tid >> 5, lane = tid & 31;
    const int s  = blockIdx.y;
    const int n0 = blockIdx.x * 128;

    float* sbias = reinterpret_cast<float*>(sm + P1_BIAS);
    if (tid < 128) sbias[tid] = bxh[n0 + tid] + bhh[n0 + tid];

    const int wm = wid >> 2, wn = wid & 3;
    const int lrow = tid >> 3, lq = tid & 7;

    auto load_stage = [&](int c, int buf) {
        const int seg  = c >> 4;
        const int koff = (c & 15) * 64 + lq * 8;
        const __nv_bfloat16* Asrc = (seg == 1) ? g_xlo  : g_xhi;
        const __nv_bfloat16* Bsrc = (seg == 2) ? g_wxlo : g_wxhi;
        uint32_t Ab = sb + buf * P1_STG + lrow * PITCH + lq * 16;
        uint32_t Bb = Ab + P1_BOFF;
#pragma unroll
        for (int i = 0; i < 4; i++) {
            int row = lrow + i * 32;
            CP16(Ab + i * 32 * PITCH, Asrc + (((size_t)((row << 8) + s)) << 10) + koff);
            CP16(Bb + i * 32 * PITCH, Bsrc + (((size_t)(n0 + row)) << 10) + koff);
        }
    };

    load_stage(0, 0); CP_COMMIT();
    load_stage(1, 1); CP_COMMIT();

    float d[4][4][4];
#pragma unroll
    for (int i = 0; i < 4; i++)
#pragma unroll
        for (int j = 0; j < 4; j++)
#pragma unroll
            for (int k = 0; k < 4; k++) d[i][j][k] = 0.0f;

    const uint32_t a_r = (uint32_t)(lane & 15) * PITCH + ((lane >> 4) << 4);
    const uint32_t b_r = (uint32_t)((lane & 7) + ((lane & 16) >> 1)) * PITCH
                       + (((lane >> 3) & 1) << 4);

    int buf = 0;
    for (int c = 0; c < NCHUNK; c++) {
        CP_WAIT1();
        __syncthreads();
        if (c + 2 < NCHUNK) load_stage(c + 2, (c + 2) % 3);
        CP_COMMIT();
        const uint32_t Ab = sb + buf * P1_STG;
        const uint32_t Bb = Ab + P1_BOFF;
#pragma unroll
        for (int s2 = 0; s2 < 4; s2++) {
            uint32_t a[4][4], b[2][4];
#pragma unroll
            for (int mt = 0; mt < 4; mt++)
                ldmx4(a[mt], Ab + (uint32_t)(wm * 64 + mt * 16) * PITCH + s2 * 32 + a_r);
#pragma unroll
            for (int nt = 0; nt < 2; nt++)
                ldmx4(b[nt], Bb + (uint32_t)(wn * 32 + nt * 16) * PITCH + s2 * 32 + b_r);
#pragma unroll
            for (int mt = 0; mt < 4; mt++)
#pragma unroll
                for (int n8 = 0; n8 < 4; n8++)
                    mma16816(d[mt][n8], a[mt], &b[n8 >> 1][(n8 & 1) * 2]);
        }
        buf = (buf == 2) ? 0 : buf + 1;
    }

    // epilogue: transpose through smem, coalesced writeout with bias
    __syncthreads();
    float* tile = reinterpret_cast<float*>(sm);  // [g:128][pitch 132]
    const int fr = lane >> 2, fc = (lane & 3) * 2;
#pragma unroll
    for (int mt = 0; mt < 4; mt++)
#pragma unroll
        for (int n8 = 0; n8 < 4; n8++) {
            int r0 = wm * 64 + mt * 16 + fr;
            int cc = wn * 32 + n8 * 8 + fc;
            tile[(size_t)cc * 132 + r0]           = d[mt][n8][0];
            tile[(size_t)(cc + 1) * 132 + r0]     = d[mt][n8][1];
            tile[(size_t)cc * 132 + r0 + 8]       = d[mt][n8][2];
            tile[(size_t)(cc + 1) * 132 + r0 + 8] = d[mt][n8][3];
        }
    __syncthreads();
#pragma unroll
    for (int it = 0; it < 16; it++) {
        int u = tid + it * 256;
        int g = u >> 5, q = u & 31;
        float4 v = *reinterpret_cast<const float4*>(tile + (size_t)g * 132 + q * 4);
        float bi = sbias[g];
        v.x += bi; v.y += bi; v.z += bi; v.w += bi;
        *reinterpret_cast<float4*>(g_xw + ((size_t)s * G4 + n0 + g) * BSZ + q * 4) = v;
    }
}

// ---------------------------------------------------------------------------
// Phase 2: one LSTM step. Grid (64, 2): j = 16-hidden-col group, mh = batch half.
// CTA: M=64 (batch) x N=64 (4 gates x 16 hidden), virtual K=3072.
// 3 buffers / 1 sync per chunk; xw[t] + c slices prefetched in group 0.
// smem: stages 0..55296 | sxw 55296(+16384) | sc 71680(+4096) | total 75776
// epilogue overlays: sg f32[64][65] @0, sh f32[64][16] @16640
// ---------------------------------------------------------------------------
#define P2_STG   18432
#define P2_BOFF  9216
#define P2_XW    55296
#define P2_C     71680
#define P2_SH    16640
#define P2_SMEM  75776

__global__ __launch_bounds__(256, 1) void lstm_tc(int t) {
    extern __shared__ char sm[];
    const uint32_t sb = smem_u32(sm);
    const int tid = threadIdx.x;
    const int wid = tid >> 5, lane = tid & 31;
    const int j = blockIdx.x;      // hidden col group (16)
    const int mh = blockIdx.y;     // batch half

    const __nv_bfloat16* __restrict__ hin_hi = g_hhi[t & 1];
    const __nv_bfloat16* __restrict__ hin_lo = g_hlo[t & 1];
    __nv_bfloat16* __restrict__ hout_hi = g_hhi[(t + 1) & 1];
    __nv_bfloat16* __restrict__ hout_lo = g_hlo[(t + 1) & 1];

    const int wm = wid >> 2, gi = wid & 3;
    const int lrow = tid >> 3, lq = tid & 7;

    auto load_stage = [&](int c, int buf) {
        const int seg  = c >> 4;
        const int koff = (c & 15) * 64 + lq * 8;
        const __nv_bfloat16* Asrc = (seg == 1) ? hin_lo : hin_hi;
        const __nv_bfloat16* Bsrc = (seg == 2) ? g_whlo : g_whhi;
        uint32_t Ab = sb + buf * P2_STG + lrow * PITCH + lq * 16;
        uint32_t Bb = Ab + P2_BOFF;
#pragma unroll
        for (int i = 0; i < 2; i++) {
            int row = lrow + i * 32;
            CP16(Ab + i * 32 * PITCH, Asrc + ((size_t)(mh * 64 + row) << 10) + koff);
            int grow = (row >> 4) * HSZ + j * 16 + (row & 15);
            CP16(Bb + i * 32 * PITCH, Bsrc + ((size_t)grow << 10) + koff);
        }
    };

    // group 0: xw slice [64 gate rows][64 b] + c slice [16 hc][64 b] + chunk 0
    {
        // xw: 1024 cp16, 4 per thread
#pragma unroll
        for (int it = 0; it < 4; it++) {
            int u = tid + it * 256;
            int gg = u >> 4, q = u & 15;
            const float* src = g_xw + ((size_t)t * G4 + (gg >> 4) * HSZ + j * 16 + (gg & 15)) * BSZ
                             + mh * 64 + q * 4;
            CP16(sb + P2_XW + gg * 256 + q * 16, src);
        }
        // c: 256 cp16, 1 per thread
        {
            int hcr = tid >> 4, q = tid & 15;
            const float* src = g_c + (size_t)(j * 16 + hcr) * BSZ + mh * 64 + q * 4;
            CP16(sb + P2_C + hcr * 256 + q * 16, src);
        }
        load_stage(0, 0); CP_COMMIT();
        load_stage(1, 1); CP_COMMIT();
    }

    float d[2][2][4];
#pragma unroll
    for (int i = 0; i < 2; i++)
#pragma unroll
        for (int jj = 0; jj < 2; jj++)
#pragma unroll
            for (int k = 0; k < 4; k++) d[i][jj][k] = 0.0f;

    const uint32_t a_r = (uint32_t)(lane & 15) * PITCH + ((lane >> 4) << 4);
    const uint32_t b_r = (uint32_t)((lane & 7) + ((lane & 16) >> 1)) * PITCH
                       + (((lane >> 3) & 1) << 4);

    int buf = 0;
    for (int c = 0; c < NCHUNK; c++) {
        CP_WAIT1();
        __syncthreads();
        if (c + 2 < NCHUNK) load_stage(c + 2, (c + 2) % 3);
        CP_COMMIT();
        const uint32_t Ab = sb + buf * P2_STG;
        const uint32_t Bb = Ab + P2_BOFF;
#pragma unroll
        for (int s2 = 0; s2 < 4; s2++) {
            uint32_t a[2][4], b[4];
#pragma unroll
            for (int mt = 0; mt < 2; mt++)
                ldmx4(a[mt], Ab + (uint32_t)(wm * 32 + mt * 16) * PITCH + s2 * 32 + a_r);
            ldmx4(b, Bb + (uint32_t)(gi * 16) * PITCH + s2 * 32 + b_r);
#pragma unroll
            for (int mt = 0; mt < 2; mt++)
#pragma unroll
                for (int n8 = 0; n8 < 2; n8++)
                    mma16816(d[mt][n8], a[mt], &b[n8 * 2]);
        }
        buf = (buf == 2) ? 0 : buf + 1;
    }

    // gates to smem: sg[b_local][gate*16 + hc], pitch 65 (overlays buf0 region)
    float* sg = reinterpret_cast<float*>(sm);
    const int fr = lane >> 2, fc = (lane & 3) * 2;
#pragma unroll
    for (int mt = 0; mt < 2; mt++)
#pragma unroll
        for (int n8 = 0; n8 < 2; n8++) {
            int r0 = wm * 32 + mt * 16 + fr;
            int cc = gi * 16 + n8 * 8 + fc;
            sg[(size_t)r0 * 65 + cc]           = d[mt][n8][0];
            sg[(size_t)r0 * 65 + cc + 1]       = d[mt][n8][1];
            sg[(size_t)(r0 + 8) * 65 + cc]     = d[mt][n8][2];
            sg[(size_t)(r0 + 8) * 65 + cc + 1] = d[mt][n8][3];
        }
    __syncthreads();

    // fused gate math: thread -> (b_local = tid&63, 4 hc values); xw & c from smem
    float* sh  = reinterpret_cast<float*>(sm + P2_SH);   // [64][16]
    float* sxw = reinterpret_cast<float*>(sm + P2_XW);   // [64 gate rows][64 b]
    float* sc  = reinterpret_cast<float*>(sm + P2_C);    // [16 hc][64 b]
    {
        const int bl = tid & 63, hq = tid >> 6;
        const int bg = mh * 64 + bl;
#pragma unroll
        for (int ii = 0; ii < 4; ii++) {
            const int hc = hq * 4 + ii;
            float vi = sg[(size_t)bl * 65 + hc]      + sxw[(0 * 16 + hc) * 64 + bl];
            float vf = sg[(size_t)bl * 65 + 16 + hc] + sxw[(1 * 16 + hc) * 64 + bl];
            float vg = sg[(size_t)bl * 65 + 32 + hc] + sxw[(2 * 16 + hc) * 64 + bl];
            float vo = sg[(size_t)bl * 65 + 48 + hc] + sxw[(3 * 16 + hc) * 64 + bl];
            float ig = sigf(vi), fg = sigf(vf), og = sigf(vo);
            float ch = tanh_fast(vg);
            float cn = sc[hc * 64 + bl] * fg + ig * ch;
            g_c[(size_t)(j * 16 + hc) * BSZ + bg] = cn;
            sh[bl * 16 + hc] = og * tanh_fast(cn);
        }
    }
    __syncthreads();

    // h writeout: split to bf16 hi/lo, 16B stores
    if (tid < 128) {
        const int b = tid >> 1, half = tid & 1;
        const float* src = sh + b * 16 + half * 8;
        __align__(16) __nv_bfloat16 hi8[8], lo8[8];
#pragma unroll
        for (int i = 0; i < 8; i++) {
            float v = src[i];
            __nv_bfloat16 h = __float2bfloat16(v);
            hi8[i] = h;
            lo8[i] = __float2bfloat16(v - __bfloat162float(h));
        }
        size_t dst = ((size_t)(mh * 64 + b) << 10) + j * 16 + half * 8;
        *reinterpret_cast<uint4*>(hout_hi + dst) = *reinterpret_cast<const uint4*>(hi8);
        *reinterpret_cast<uint4*>(hout_lo + dst) = *reinterpret_cast<const uint4*>(lo8);
    }
}

// ---------------------------------------------------------------------------
// Phase 3: out[b][c] = h_last . Wfc[c] + bfc[c]
// ---------------------------------------------------------------------------
__global__ __launch_bounds__(256) void fc_out(const float* __restrict__ Wfc,
                                              const float* __restrict__ bfc,
                                              float* __restrict__ out) {
    __shared__ float hs[HSZ];
    const int b = blockIdx.x;
    for (int i = threadIdx.x; i < HSZ; i += 256)
        hs[i] = __bfloat162float(g_hhi[0][b * HSZ + i]) + __bfloat162float(g_hlo[0][b * HSZ + i]);
    __syncthreads();

    for (int cc = threadIdx.x; cc < CSZ; cc += 256) {
        const float* wr = Wfc + (size_t)cc * HSZ;
        float acc = 0.0f;
#pragma unroll 4
        for (int k = 0; k < HSZ; k += 4) {
            float4 w = *reinterpret_cast<const float4*>(wr + k);
            acc = fmaf(hs[k + 0], w.x, acc);
            acc = fmaf(hs[k + 1], w.y, acc);
            acc = fmaf(hs[k + 2], w.z, acc);
            acc = fmaf(hs[k + 3], w.w, acc);
        }
        out[b * CSZ + cc] = acc + bfc[cc];
    }
}

// ---------------------------------------------------------------------------
// launch
// ---------------------------------------------------------------------------
extern "C" void kernel_launch(void* const* d_in, const int* in_sizes, int n_in,
                              void* d_out, int out_size) {
    const float* x   = (const float*)d_in[0];
    const float* Wxh = (const float*)d_in[1];
    const float* bxh = (const float*)d_in[2];
    const float* Whh = (const float*)d_in[3];
    const float* bhh = (const float*)d_in[4];
    const float* Wfc = (const float*)d_in[5];
    const float* bfc = (const float*)d_in[6];
    float* out = (float*)d_out;

    cudaFuncSetAttribute(gemm_xw_tc, cudaFuncAttributeMaxDynamicSharedMemorySize, P1_SMEM);
    cudaFuncSetAttribute(lstm_tc,    cudaFuncAttributeMaxDynamicSharedMemorySize, P2_SMEM);

    {
        int n4 = (BSZ * SSZ * ISZ) / 4;
        split_k<<<(n4 + 255) / 256, 256>>>(x, 0, n4);
        n4 = (G4 * ISZ) / 4;
        split_k<<<(n4 + 255) / 256, 256>>>(Wxh, 1, n4);
        n4 = (G4 * HSZ) / 4;
        split_k<<<(n4 + 255) / 256, 256>>>(Whh, 2, n4);
    }
    init_state<<<(BSZ * HSZ + 255) / 256, 256>>>();

    dim3 g1(G4 / 128, SSZ);   // (32, 256)
    gemm_xw_tc<<<g1, 256, P1_SMEM>>>(bxh, bhh);

    dim3 g2(HSZ / 16, 2);     // (64, 2)
    for (int t = 0; t < SSZ; t++)
        lstm_tc<<<g2, 256, P2_SMEM>>>(t);

    fc_out<<<BSZ, 256>>>(Wfc, bfc, out);
}